// round 15
// baseline (speedup 1.0000x reference)
#include <cuda_runtime.h>
#include <cuda_bf16.h>
#include <cuda_fp16.h>
#include <cstdint>
#include <cstddef>

#define NN 100000
#define DD 128
#define CC 40
#define EMAX 1048576

// ---------------- scratch (static __device__ globals, no allocation) ----------------
__device__ float g_h[(size_t)NN * DD];
__device__ __half g_h16[(size_t)NN * DD];   // fp16 shadow of h for agg gathers
__device__ float g_agg[(size_t)NN * DD];
__device__ float g_feat[(size_t)NN * DD];
__device__ float g_dinv[NN];
__device__ int   g_degi[NN];
__device__ int   g_row_ptr[NN];            // block-local exclusive prefix
__device__ int   g_cnt2[NN];               // fill cursors
__device__ int   g_col[EMAX];
__device__ int   g_bsum[512];
__device__ int   g_boff[512];
__device__ float g_statsAll[3 * 256];
__device__ float g_mu[DD];
__device__ float g_rstd[DD];
__device__ int   g_done[4];
__device__ int   g_is64;
__device__ uint4 g_BF[3][4096];
__device__ uint4 g_BFo[2048];

// ---------------- PTX helpers (arch-generic only) ----------------
__device__ __forceinline__ uint32_t smem_u32(const void* p) {
    uint32_t a;
    asm("{ .reg .u64 t; cvta.to.shared.u64 t, %1; cvt.u32.u64 %0, t; }" : "=r"(a) : "l"(p));
    return a;
}
#define LDSM_X4(r, addr) \
    asm volatile("ldmatrix.sync.aligned.m8n8.x4.shared.b16 {%0,%1,%2,%3}, [%4];" \
                 : "=r"((r)[0]), "=r"((r)[1]), "=r"((r)[2]), "=r"((r)[3]) : "r"(addr))
#define MMA16816(c, a, b0, b1) \
    asm volatile("mma.sync.aligned.m16n8k16.row.col.f32.bf16.bf16.f32 " \
                 "{%0,%1,%2,%3},{%4,%5,%6,%7},{%8,%9},{%0,%1,%2,%3};" \
                 : "+f"((c)[0]), "+f"((c)[1]), "+f"((c)[2]), "+f"((c)[3]) \
                 : "r"((a)[0]), "r"((a)[1]), "r"((a)[2]), "r"((a)[3]), "r"(b0), "r"(b1))

__device__ __forceinline__ uint32_t pack2(float a, float b) {
    __nv_bfloat162 t = __floats2bfloat162_rn(a, b);
    return *(uint32_t*)&t;
}
__device__ __forceinline__ uint32_t packbf(__nv_bfloat16 a, __nv_bfloat16 b) {
    __nv_bfloat162 t; t.x = a; t.y = b;
    return *(uint32_t*)&t;
}
__device__ __forceinline__ int edge_at(const void* edges, long long i) {
    if (g_is64) return (int)((const long long*)edges)[i];
    return ((const int*)edges)[i];
}

// ---------------- fused prep: fragments + head + detect + zero-init ----------------
__global__ void prep_kernel(const float* __restrict__ W1, const float* __restrict__ W2,
                            const float* __restrict__ W3, const float* __restrict__ Wout,
                            const void* edges) {
    int b = blockIdx.x;
    int t = threadIdx.x;
    if (b < 24) {
        int layer = b >> 3;
        const float* W = (layer == 0) ? W1 : ((layer == 1) ? W2 : W3);
        int idx = (b & 7) * 512 + t;
        int lane = idx & 31;
        int p = (idx >> 5) & 3;
        int ks = (idx >> 7) & 7;
        int ng = (idx >> 10) & 1;
        int s = (idx >> 11) & 1;
        int n0 = ng * 64 + p * 16 + (lane >> 2);
        int k0 = ks * 16 + (lane & 3) * 2;
        __nv_bfloat16 v[8];
#pragma unroll
        for (int dk = 0; dk < 2; dk++)
#pragma unroll
            for (int kk = 0; kk < 2; kk++)
#pragma unroll
                for (int dn = 0; dn < 2; dn++) {
                    float w = W[(k0 + dk * 8 + kk) * DD + n0 + dn * 8];
                    __nv_bfloat16 hi = __float2bfloat16(w);
                    __nv_bfloat16 r = (s == 0) ? hi : __float2bfloat16(w - __bfloat162float(hi));
                    v[dk * 4 + dn * 2 + kk] = r;
                }
        g_BF[layer][idx] = make_uint4(packbf(v[0], v[1]), packbf(v[2], v[3]),
                                      packbf(v[4], v[5]), packbf(v[6], v[7]));
    } else if (b == 24) {
#pragma unroll
        for (int it = 0; it < 4; it++) {
            int idx = it * 512 + t;
            int lane = idx & 31;
            int p = (idx >> 5) & 3;
            int ks = (idx >> 7) & 7;
            int s = (idx >> 10) & 1;
            int n0 = p * 16 + (lane >> 2);
            int k0 = ks * 16 + (lane & 3) * 2;
            __nv_bfloat16 v[8];
#pragma unroll
            for (int dk = 0; dk < 2; dk++)
#pragma unroll
                for (int kk = 0; kk < 2; kk++)
#pragma unroll
                    for (int dn = 0; dn < 2; dn++) {
                        int n = n0 + dn * 8;
                        float w = (n < CC) ? Wout[(k0 + dk * 8 + kk) * CC + n] : 0.0f;
                        __nv_bfloat16 hi = __float2bfloat16(w);
                        __nv_bfloat16 r = (s == 0) ? hi : __float2bfloat16(w - __bfloat162float(hi));
                        v[dk * 4 + dn * 2 + kk] = r;
                    }
            g_BFo[idx] = make_uint4(packbf(v[0], v[1]), packbf(v[2], v[3]),
                                    packbf(v[4], v[5]), packbf(v[6], v[7]));
        }
        if (t < 32) {
            const long long* p64 = (const long long*)edges;
            int ok = 1;
            for (int j = 0; j < 16; j++) {
                long long v = p64[t + j * 32];
                if (v < 0 || v >= NN) ok = 0;
            }
            ok = __all_sync(0xFFFFFFFFu, ok);
            if (t == 0) g_is64 = ok;
        }
    } else {
        int b2 = b - 25;  // 0..97
#pragma unroll
        for (int q = 0; q < 2; q++) {
            int i = b2 * 1024 + q * 512 + t;
            if (i < NN) { g_degi[i] = 0; g_cnt2[i] = 0; }
        }
        if (b2 == 0) {
            if (t < 384) { g_statsAll[t] = 0.0f; g_statsAll[t + 384] = 0.0f; }
            if (t < 4) g_done[t] = 0;
        }
    }
}

// ---------------- degree count ----------------
__global__ void deg_count_kernel(const void* edges, int E) {
    int e = blockIdx.x * blockDim.x + threadIdx.x;
    if (e >= E) return;
    atomicAdd(&g_degi[edge_at(edges, (long long)E + e)], 1);
}

// ---------------- fused scan: block-local prefix + dinv; last block scans bsums ----------------
__global__ void scanA_kernel(int nblk) {
    __shared__ int sh[256];
    __shared__ int isLast;
    int t = threadIdx.x;
    int i = blockIdx.x * 256 + t;
    int v = (i < NN) ? g_degi[i] : 0;
    sh[t] = v;
    __syncthreads();
    int acc = v;
#pragma unroll
    for (int o = 1; o < 256; o <<= 1) {
        int add = (t >= o) ? sh[t - o] : 0;
        __syncthreads();
        acc += add;
        sh[t] = acc;
        __syncthreads();
    }
    if (i < NN) {
        g_row_ptr[i] = acc - v;
        g_dinv[i] = rsqrtf(1.0f + (float)v);
    }
    if (t == 255) {
        g_bsum[blockIdx.x] = acc;
        __threadfence();
        int tk = atomicAdd(&g_done[3], 1);
        isLast = (tk == (int)gridDim.x - 1);
    }
    __syncthreads();
    if (isLast && t < 32) {
        int base = t * 13;
        int vals[13];
        int s = 0;
#pragma unroll
        for (int q = 0; q < 13; q++) {
            int idx = base + q;
            vals[q] = (idx < nblk) ? __ldcg(&g_bsum[idx]) : 0;
            s += vals[q];
        }
        int incl = s;
#pragma unroll
        for (int o = 1; o < 32; o <<= 1) {
            int n = __shfl_up_sync(0xFFFFFFFFu, incl, o);
            if (t >= o) incl += n;
        }
        int run = incl - s;
#pragma unroll
        for (int q = 0; q < 13; q++) {
            int idx = base + q;
            if (idx < nblk) g_boff[idx] = run;
            run += vals[q];
        }
    }
}

// ---------------- CSR fill (boff inline) ----------------
__global__ void fill_kernel(const void* edges, int E) {
    int e = blockIdx.x * blockDim.x + threadIdx.x;
    if (e >= E) return;
    int s = edge_at(edges, e);
    int d = edge_at(edges, (long long)E + e);
    int rp = g_row_ptr[d] + g_boff[d >> 8];
    g_col[rp + atomicAdd(&g_cnt2[d], 1)] = s;
}

// ---------------- staging: 128 rows -> hi/lo bf16 images; optional fused normalize ----------------
__device__ __forceinline__ void stage128(const float* __restrict__ src, int row0,
                                         char* sA, int tid, int mode, int hasRes, int writeFeat,
                                         const float* __restrict__ gamma,
                                         const float* __restrict__ beta) {
#pragma unroll
    for (int j = 0; j < 8; j++) {
        int i = tid + j * 256;
        int rl = i >> 4;
        int c = i & 15;
        int rr = row0 + rl;
        int valid = rr < NN;
        float4 y0 = make_float4(0, 0, 0, 0), y1 = make_float4(0, 0, 0, 0);
        if (valid) {
            const float* sp = src + (size_t)rr * DD + c * 8;
            y0 = *(const float4*)sp;
            y1 = *(const float4*)(sp + 4);
        }
        if (mode) {
            float4 mu0 = ((const float4*)g_mu)[c * 2], mu1 = ((const float4*)g_mu)[c * 2 + 1];
            float4 rs0 = ((const float4*)g_rstd)[c * 2], rs1 = ((const float4*)g_rstd)[c * 2 + 1];
            float4 gm0 = ((const float4*)gamma)[c * 2], gm1 = ((const float4*)gamma)[c * 2 + 1];
            float4 be0 = ((const float4*)beta)[c * 2], be1v = ((const float4*)beta)[c * 2 + 1];
            y0.x = fmaxf(0.0f, (y0.x - mu0.x) * rs0.x * gm0.x + be0.x);
            y0.y = fmaxf(0.0f, (y0.y - mu0.y) * rs0.y * gm0.y + be0.y);
            y0.z = fmaxf(0.0f, (y0.z - mu0.z) * rs0.z * gm0.z + be0.z);
            y0.w = fmaxf(0.0f, (y0.w - mu0.w) * rs0.w * gm0.w + be0.w);
            y1.x = fmaxf(0.0f, (y1.x - mu1.x) * rs1.x * gm1.x + be1v.x);
            y1.y = fmaxf(0.0f, (y1.y - mu1.y) * rs1.y * gm1.y + be1v.y);
            y1.z = fmaxf(0.0f, (y1.z - mu1.z) * rs1.z * gm1.z + be1v.z);
            y1.w = fmaxf(0.0f, (y1.w - mu1.w) * rs1.w * gm1.w + be1v.w);
            if (hasRes && valid) {
                const float* rp = g_feat + (size_t)rr * DD + c * 8;
                float4 r0 = *(const float4*)rp, r1 = *(const float4*)(rp + 4);
                y0.x += r0.x; y0.y += r0.y; y0.z += r0.z; y0.w += r0.w;
                y1.x += r1.x; y1.y += r1.y; y1.z += r1.z; y1.w += r1.w;
            }
            float ss = y0.x * y0.x + y0.y * y0.y + y0.z * y0.z + y0.w * y0.w +
                       y1.x * y1.x + y1.y * y1.y + y1.z * y1.z + y1.w * y1.w;
#pragma unroll
            for (int o = 1; o < 16; o <<= 1) ss += __shfl_xor_sync(0xFFFFFFFFu, ss, o);
            float inv = 1.0f / fmaxf(sqrtf(ss), 1e-12f);
            y0.x *= inv; y0.y *= inv; y0.z *= inv; y0.w *= inv;
            y1.x *= inv; y1.y *= inv; y1.z *= inv; y1.w *= inv;
            if (writeFeat && valid) {
                float* fp = g_feat + (size_t)rr * DD + c * 8;
                *(float4*)fp = y0;
                *(float4*)(fp + 4) = y1;
            }
        }
        __nv_bfloat16 h0 = __float2bfloat16(y0.x), h1 = __float2bfloat16(y0.y);
        __nv_bfloat16 h2 = __float2bfloat16(y0.z), h3 = __float2bfloat16(y0.w);
        __nv_bfloat16 h4 = __float2bfloat16(y1.x), h5 = __float2bfloat16(y1.y);
        __nv_bfloat16 h6 = __float2bfloat16(y1.z), h7 = __float2bfloat16(y1.w);
        uint4 hv = make_uint4(packbf(h0, h1), packbf(h2, h3), packbf(h4, h5), packbf(h6, h7));
        uint4 lv = make_uint4(
            pack2(y0.x - __bfloat162float(h0), y0.y - __bfloat162float(h1)),
            pack2(y0.z - __bfloat162float(h2), y0.w - __bfloat162float(h3)),
            pack2(y1.x - __bfloat162float(h4), y1.y - __bfloat162float(h5)),
            pack2(y1.z - __bfloat162float(h6), y1.w - __bfloat162float(h7)));
        uint32_t off = (uint32_t)rl * 256u + (((uint32_t)(c ^ (rl & 7))) << 4);
        *(uint4*)(sA + off) = hv;
        *(uint4*)(sA + 32768 + off) = lv;
    }
}

// ---------------- main GEMM: fused 3-pass mainloop, M=128 tiles ----------------
#define SMG_TOTAL 65536
__global__ __launch_bounds__(256, 2) void gemm_mma_kernel(const float* __restrict__ src, int layer,
                                                          int mode, int hasRes, int writeFeat,
                                                          const float* __restrict__ gamma,
                                                          const float* __restrict__ beta) {
    extern __shared__ char smem[];
    uint32_t sb = smem_u32(smem);
    int tid = threadIdx.x, lane = tid & 31, wid = tid >> 5;
    int row0 = blockIdx.x * 128;

    stage128(src, row0, smem, tid, mode, hasRes, writeFeat, gamma, beta);
    __syncthreads();

    const int wm = (wid & 3) * 32;
    const int ng = wid >> 2;
    float acc[2][8][4];
#pragma unroll
    for (int mt = 0; mt < 2; mt++)
#pragma unroll
        for (int nt = 0; nt < 8; nt++)
#pragma unroll
            for (int q = 0; q < 4; q++) acc[mt][nt][q] = 0.0f;

    const uint4* __restrict__ BFh = g_BF[layer] + (ng * 8) * 128 + lane;
    const uint4* __restrict__ BFl = g_BF[layer] + ((2 + ng) * 8) * 128 + lane;

#pragma unroll
    for (int ks = 0; ks < 8; ks++) {
        uint32_t ah[2][4], al[2][4];
#pragma unroll
        for (int mt = 0; mt < 2; mt++) {
            int m = wm + mt * 16 + (lane & 15);
            uint32_t addr = sb + m * 256 + ((((ks << 1) | (lane >> 4)) ^ (m & 7)) << 4);
            LDSM_X4(ah[mt], addr);
            LDSM_X4(al[mt], addr + 32768);
        }
        uint4 bh[4];
#pragma unroll
        for (int p = 0; p < 4; p++) bh[p] = BFh[ks * 128 + p * 32];
#pragma unroll
        for (int p = 0; p < 4; p++)
#pragma unroll
            for (int mt = 0; mt < 2; mt++) {
                MMA16816(acc[mt][2 * p], ah[mt], bh[p].x, bh[p].z);
                MMA16816(acc[mt][2 * p + 1], ah[mt], bh[p].y, bh[p].w);
            }
#pragma unroll
        for (int p = 0; p < 4; p++)
#pragma unroll
            for (int mt = 0; mt < 2; mt++) {
                MMA16816(acc[mt][2 * p], al[mt], bh[p].x, bh[p].z);
                MMA16816(acc[mt][2 * p + 1], al[mt], bh[p].y, bh[p].w);
            }
        uint4 bl[4];
#pragma unroll
        for (int p = 0; p < 4; p++) bl[p] = BFl[ks * 128 + p * 32];
#pragma unroll
        for (int p = 0; p < 4; p++)
#pragma unroll
            for (int mt = 0; mt < 2; mt++) {
                MMA16816(acc[mt][2 * p], ah[mt], bl[p].x, bl[p].z);
                MMA16816(acc[mt][2 * p + 1], ah[mt], bl[p].y, bl[p].w);
            }
    }

#pragma unroll
    for (int mt = 0; mt < 2; mt++) {
        int rA = row0 + wm + mt * 16 + (lane >> 2);
        int rB = rA + 8;
#pragma unroll
        for (int nt = 0; nt < 8; nt++) {
            int col = ng * 64 + nt * 8 + (lane & 3) * 2;
            if (rA < NN) {
                *(float2*)(g_h + (size_t)rA * DD + col) = make_float2(acc[mt][nt][0], acc[mt][nt][1]);
                *(__half2*)(g_h16 + (size_t)rA * DD + col) =
                    __floats2half2_rn(acc[mt][nt][0], acc[mt][nt][1]);
            }
            if (rB < NN) {
                *(float2*)(g_h + (size_t)rB * DD + col) = make_float2(acc[mt][nt][2], acc[mt][nt][3]);
                *(__half2*)(g_h16 + (size_t)rB * DD + col) =
                    __floats2half2_rn(acc[mt][nt][2], acc[mt][nt][3]);
            }
        }
    }
}

// ---------------- output head ----------------
__global__ __launch_bounds__(256, 2) void head_kernel(const float* __restrict__ bout,
                                                      float* __restrict__ out,
                                                      const float* __restrict__ gamma,
                                                      const float* __restrict__ beta) {
    extern __shared__ char smem[];
    uint32_t sb = smem_u32(smem);
    int tid = threadIdx.x, lane = tid & 31, wid = tid >> 5;
    int row0 = blockIdx.x * 128;

    stage128(g_agg, row0, smem, tid, 1, 1, 0, gamma, beta);
    __syncthreads();

    const int wm = (wid & 3) * 32;
    const int ng = wid >> 2;
    float acc[2][4][4];
#pragma unroll
    for (int mt = 0; mt < 2; mt++)
#pragma unroll
        for (int nt = 0; nt < 4; nt++)
#pragma unroll
            for (int q = 0; q < 4; q++) acc[mt][nt][q] = 0.0f;

    const uint4* __restrict__ BFh = g_BFo + lane;
    const uint4* __restrict__ BFl = g_BFo + 8 * 128 + lane;

#pragma unroll
    for (int ks = 0; ks < 8; ks++) {
        uint32_t ah[2][4], al[2][4];
#pragma unroll
        for (int mt = 0; mt < 2; mt++) {
            int m = wm + mt * 16 + (lane & 15);
            uint32_t addr = sb + m * 256 + ((((ks << 1) | (lane >> 4)) ^ (m & 7)) << 4);
            LDSM_X4(ah[mt], addr);
            LDSM_X4(al[mt], addr + 32768);
        }
        uint4 bh[2], bl[2];
#pragma unroll
        for (int pp = 0; pp < 2; pp++) {
            int p = ng * 2 + pp;
            bh[pp] = BFh[ks * 128 + p * 32];
            bl[pp] = BFl[ks * 128 + p * 32];
        }
#pragma unroll
        for (int pp = 0; pp < 2; pp++)
#pragma unroll
            for (int mt = 0; mt < 2; mt++) {
                MMA16816(acc[mt][2 * pp], ah[mt], bh[pp].x, bh[pp].z);
                MMA16816(acc[mt][2 * pp + 1], ah[mt], bh[pp].y, bh[pp].w);
                MMA16816(acc[mt][2 * pp], al[mt], bh[pp].x, bh[pp].z);
                MMA16816(acc[mt][2 * pp + 1], al[mt], bh[pp].y, bh[pp].w);
                MMA16816(acc[mt][2 * pp], ah[mt], bl[pp].x, bl[pp].z);
                MMA16816(acc[mt][2 * pp + 1], ah[mt], bl[pp].y, bl[pp].w);
            }
    }

#pragma unroll
    for (int mt = 0; mt < 2; mt++) {
        int rA = row0 + wm + mt * 16 + (lane >> 2);
        int rB = rA + 8;
#pragma unroll
        for (int pp = 0; pp < 2; pp++)
#pragma unroll
            for (int q = 0; q < 2; q++) {
                int col = (ng * 2 + pp) * 16 + q * 8 + (lane & 3) * 2;
                float* a4 = acc[mt][2 * pp + q];
                if (col < CC) {
                    float b0 = bout[col], b1 = bout[col + 1];
                    if (rA < NN)
                        *(float2*)(out + (size_t)rA * CC + col) = make_float2(a4[0] + b0, a4[1] + b1);
                    if (rB < NN)
                        *(float2*)(out + (size_t)rB * CC + col) = make_float2(a4[2] + b0, a4[3] + b1);
                }
            }
    }
}

// ---------------- CSR aggregation (warp per row, 8 rows/warp, fp16 gathers) ----------------
__global__ __launch_bounds__(256) void agg_kernel(int layer, int E) {
    __shared__ float ssum[128], ssq[128];
    __shared__ int isLast;
    int tid = threadIdx.x;
    if (tid < 128) { ssum[tid] = 0.0f; ssq[tid] = 0.0f; }
    __syncthreads();
    int wid = tid >> 5, lane = tid & 31;
    float4 psum = make_float4(0, 0, 0, 0);
    float4 psq = make_float4(0, 0, 0, 0);
    int rbase = blockIdx.x * 64 + wid * 8;
#pragma unroll 1
    for (int it = 0; it < 8; it++) {
        int r = rbase + it;
        if (r >= NN) break;
        int beg = g_row_ptr[r] + g_boff[r >> 8];
        int end = (r == NN - 1) ? E : (g_row_ptr[r + 1] + g_boff[(r + 1) >> 8]);
        float dr = g_dinv[r];
        float4 acc = ((const float4*)(g_h + (size_t)r * DD))[lane];
        float d2 = dr * dr;
        acc.x *= d2; acc.y *= d2; acc.z *= d2; acc.w *= d2;
        for (int base = beg; base < end; base += 8) {
            int m = end - base;
            if (m > 8) m = 8;
            int c = 0;
            float w = 0.0f;
            if (lane < m) { c = g_col[base + lane]; w = g_dinv[c] * dr; }
            uint2 vv[8];
#pragma unroll
            for (int j = 0; j < 8; j++)
                if (j < m) {
                    int sj = __shfl_sync(0xFFFFFFFFu, c, j);
                    vv[j] = __ldg((const uint2*)(g_h16 + (size_t)sj * DD + lane * 4));
                }
#pragma unroll
            for (int j = 0; j < 8; j++)
                if (j < m) {
                    float wj = __shfl_sync(0xFFFFFFFFu, w, j);
                    float2 f01 = __half22float2(*(__half2*)&vv[j].x);
                    float2 f23 = __half22float2(*(__half2*)&vv[j].y);
                    acc.x += f01.x * wj; acc.y += f01.y * wj;
                    acc.z += f23.x * wj; acc.w += f23.y * wj;
                }
        }
        ((float4*)(g_agg + (size_t)r * DD))[lane] = acc;
        psum.x += acc.x; psum.y += acc.y; psum.z += acc.z; psum.w += acc.w;
        psq.x += acc.x * acc.x; psq.y += acc.y * acc.y;
        psq.z += acc.z * acc.z; psq.w += acc.w * acc.w;
    }
    int c0 = lane * 4;
    atomicAdd(&ssum[c0 + 0], psum.x); atomicAdd(&ssum[c0 + 1], psum.y);
    atomicAdd(&ssum[c0 + 2], psum.z); atomicAdd(&ssum[c0 + 3], psum.w);
    atomicAdd(&ssq[c0 + 0], psq.x);  atomicAdd(&ssq[c0 + 1], psq.y);
    atomicAdd(&ssq[c0 + 2], psq.z);  atomicAdd(&ssq[c0 + 3], psq.w);
    __syncthreads();
    if (tid < 128) {
        atomicAdd(&g_statsAll[layer * 256 + tid], ssum[tid]);
        atomicAdd(&g_statsAll[layer * 256 + 128 + tid], ssq[tid]);
    }
    __threadfence();
    if (tid == 0) {
        int tk = atomicAdd(&g_done[layer], 1);
        isLast = (tk == (int)gridDim.x - 1);
    }
    __syncthreads();
    if (isLast && tid < 128) {
        float inv_n = 1.0f / (float)NN;
        float mu = __ldcg(&g_statsAll[layer * 256 + tid]) * inv_n;
        float var = __ldcg(&g_statsAll[layer * 256 + 128 + tid]) * inv_n - mu * mu;
        g_mu[tid] = mu;
        g_rstd[tid] = rsqrtf(var + 1e-5f);
    }
}

// ---------------- launch (two-stream overlap: CSR build || gemm1) ----------------
extern "C" void kernel_launch(void* const* d_in, const int* in_sizes, int n_in,
                              void* d_out, int out_size) {
    const float* x    = (const float*)d_in[0];
    const void*  edges = d_in[1];
    const float* W1   = (const float*)d_in[2];
    const float* W2   = (const float*)d_in[4];
    const float* W3   = (const float*)d_in[6];
    const float* g1   = (const float*)d_in[8];
    const float* be1  = (const float*)d_in[9];
    const float* g2   = (const float*)d_in[10];
    const float* be2  = (const float*)d_in[11];
    const float* g3   = (const float*)d_in[12];
    const float* be3  = (const float*)d_in[13];
    const float* Wout = (const float*)d_in[14];
    const float* bout = (const float*)d_in[15];
    float* out = (float*)d_out;
    int E = in_sizes[1] / 2;

    float* aggp = nullptr;
    cudaGetSymbolAddress((void**)&aggp, g_agg);

    cudaFuncSetAttribute(gemm_mma_kernel, cudaFuncAttributeMaxDynamicSharedMemorySize, SMG_TOTAL);
    cudaFuncSetAttribute(head_kernel, cudaFuncAttributeMaxDynamicSharedMemorySize, SMG_TOTAL);

    // lazily-created side stream + events (host-side handles only; no device memory)
    static cudaStream_t s1 = nullptr;
    static cudaEvent_t evFork = nullptr, evJoin = nullptr;
    if (s1 == nullptr) {
        cudaStreamCreateWithFlags(&s1, cudaStreamNonBlocking);
        cudaEventCreateWithFlags(&evFork, cudaEventDisableTiming);
        cudaEventCreateWithFlags(&evJoin, cudaEventDisableTiming);
    }

    int nblk = (NN + 255) / 256;      // 391
    int gblk = (NN + 127) / 128;      // 782
    int eblk = (E + 255) / 256;
    int agg_blk = (NN + 63) / 64;     // 1563

    // main stream: prep -> gemm1 ; side stream: deg_count -> scanA -> fill
    prep_kernel<<<123, 512>>>(W1, W2, W3, Wout, edges);
    cudaEventRecord(evFork, 0);
    cudaStreamWaitEvent(s1, evFork, 0);
    deg_count_kernel<<<eblk, 256, 0, s1>>>(edges, E);
    scanA_kernel<<<nblk, 256, 0, s1>>>(nblk);
    gemm_mma_kernel<<<gblk, 256, SMG_TOTAL>>>(x, 0, 0, 0, 0, nullptr, nullptr);  // launch #4 (ncu slot)
    fill_kernel<<<eblk, 256, 0, s1>>>(edges, E);
    cudaEventRecord(evJoin, s1);
    cudaStreamWaitEvent(0, evJoin, 0);

    agg_kernel<<<agg_blk, 256>>>(0, E);
    gemm_mma_kernel<<<gblk, 256, SMG_TOTAL>>>(aggp, 1, 1, 0, 1, g1, be1);

    agg_kernel<<<agg_blk, 256>>>(1, E);
    gemm_mma_kernel<<<gblk, 256, SMG_TOTAL>>>(aggp, 2, 1, 1, 1, g2, be2);

    agg_kernel<<<agg_blk, 256>>>(2, E);
    head_kernel<<<gblk, 256, SMG_TOTAL>>>(bout, out, g3, be3);
}

// round 16
// speedup vs baseline: 1.0937x; 1.0937x over previous
#include <cuda_runtime.h>
#include <cuda_bf16.h>
#include <cstdint>
#include <cstddef>

#define NN 100000
#define DD 128
#define CC 40
#define EMAX 1048576

// ---------------- scratch (static __device__ globals, no allocation) ----------------
__device__ float g_h[(size_t)NN * DD];
__device__ float g_agg[(size_t)NN * DD];
__device__ float g_feat[(size_t)NN * DD];
__device__ float g_dinv[NN];
__device__ int   g_degi[NN];
__device__ int   g_row_ptr[NN];            // block-local exclusive prefix
__device__ int   g_cnt2[NN];               // fill cursors
__device__ int   g_col[EMAX];
__device__ int   g_bsum[512];
__device__ int   g_boff[512];
__device__ float g_statsAll[3 * 256];
__device__ float g_mu[DD];
__device__ float g_rstd[DD];
__device__ int   g_done[4];
__device__ int   g_is64;
__device__ uint4 g_BF[3][4096];
__device__ uint4 g_BFo[2048];

// ---------------- PTX helpers (arch-generic only) ----------------
__device__ __forceinline__ uint32_t smem_u32(const void* p) {
    uint32_t a;
    asm("{ .reg .u64 t; cvta.to.shared.u64 t, %1; cvt.u32.u64 %0, t; }" : "=r"(a) : "l"(p));
    return a;
}
#define LDSM_X4(r, addr) \
    asm volatile("ldmatrix.sync.aligned.m8n8.x4.shared.b16 {%0,%1,%2,%3}, [%4];" \
                 : "=r"((r)[0]), "=r"((r)[1]), "=r"((r)[2]), "=r"((r)[3]) : "r"(addr))
#define MMA16816(c, a, b0, b1) \
    asm volatile("mma.sync.aligned.m16n8k16.row.col.f32.bf16.bf16.f32 " \
                 "{%0,%1,%2,%3},{%4,%5,%6,%7},{%8,%9},{%0,%1,%2,%3};" \
                 : "+f"((c)[0]), "+f"((c)[1]), "+f"((c)[2]), "+f"((c)[3]) \
                 : "r"((a)[0]), "r"((a)[1]), "r"((a)[2]), "r"((a)[3]), "r"(b0), "r"(b1))

__device__ __forceinline__ uint32_t pack2(float a, float b) {
    __nv_bfloat162 t = __floats2bfloat162_rn(a, b);
    return *(uint32_t*)&t;
}
__device__ __forceinline__ uint32_t packbf(__nv_bfloat16 a, __nv_bfloat16 b) {
    __nv_bfloat162 t; t.x = a; t.y = b;
    return *(uint32_t*)&t;
}
__device__ __forceinline__ int edge_at(const void* edges, long long i) {
    if (g_is64) return (int)((const long long*)edges)[i];
    return ((const int*)edges)[i];
}

// ---------------- init: zeroing + dtype detect (feeds the side-stream CSR chain) ----------------
__global__ void init_kernel(const void* edges) {
    int b = blockIdx.x;
    int t = threadIdx.x;
    if (b < 98) {
#pragma unroll
        for (int q = 0; q < 2; q++) {
            int i = b * 1024 + q * 512 + t;
            if (i < NN) { g_degi[i] = 0; g_cnt2[i] = 0; }
        }
    } else {
        if (t < 384) { g_statsAll[t] = 0.0f; g_statsAll[t + 384] = 0.0f; }
        if (t < 4) g_done[t] = 0;
        if (t >= 480) {  // one warp: detect
            int lane = t - 480;
            const long long* p64 = (const long long*)edges;
            int ok = 1;
            for (int j = 0; j < 16; j++) {
                long long v = p64[lane + j * 32];
                if (v < 0 || v >= NN) ok = 0;
            }
            ok = __all_sync(0xFFFFFFFFu, ok);
            if (lane == 0) g_is64 = ok;
        }
    }
}

// ---------------- W fragment prep (runs on main stream, overlapped with CSR build) ----------------
__global__ void prepw_kernel(const float* __restrict__ W1, const float* __restrict__ W2,
                             const float* __restrict__ W3, const float* __restrict__ Wout) {
    int b = blockIdx.x;
    int t = threadIdx.x;
    if (b < 24) {
        int layer = b >> 3;
        const float* W = (layer == 0) ? W1 : ((layer == 1) ? W2 : W3);
        int idx = (b & 7) * 512 + t;
        int lane = idx & 31;
        int p = (idx >> 5) & 3;
        int ks = (idx >> 7) & 7;
        int ng = (idx >> 10) & 1;
        int s = (idx >> 11) & 1;
        int n0 = ng * 64 + p * 16 + (lane >> 2);
        int k0 = ks * 16 + (lane & 3) * 2;
        __nv_bfloat16 v[8];
#pragma unroll
        for (int dk = 0; dk < 2; dk++)
#pragma unroll
            for (int kk = 0; kk < 2; kk++)
#pragma unroll
                for (int dn = 0; dn < 2; dn++) {
                    float w = W[(k0 + dk * 8 + kk) * DD + n0 + dn * 8];
                    __nv_bfloat16 hi = __float2bfloat16(w);
                    __nv_bfloat16 r = (s == 0) ? hi : __float2bfloat16(w - __bfloat162float(hi));
                    v[dk * 4 + dn * 2 + kk] = r;
                }
        g_BF[layer][idx] = make_uint4(packbf(v[0], v[1]), packbf(v[2], v[3]),
                                      packbf(v[4], v[5]), packbf(v[6], v[7]));
    } else {
#pragma unroll
        for (int it = 0; it < 4; it++) {
            int idx = it * 512 + t;
            int lane = idx & 31;
            int p = (idx >> 5) & 3;
            int ks = (idx >> 7) & 7;
            int s = (idx >> 10) & 1;
            int n0 = p * 16 + (lane >> 2);
            int k0 = ks * 16 + (lane & 3) * 2;
            __nv_bfloat16 v[8];
#pragma unroll
            for (int dk = 0; dk < 2; dk++)
#pragma unroll
                for (int kk = 0; kk < 2; kk++)
#pragma unroll
                    for (int dn = 0; dn < 2; dn++) {
                        int n = n0 + dn * 8;
                        float w = (n < CC) ? Wout[(k0 + dk * 8 + kk) * CC + n] : 0.0f;
                        __nv_bfloat16 hi = __float2bfloat16(w);
                        __nv_bfloat16 r = (s == 0) ? hi : __float2bfloat16(w - __bfloat162float(hi));
                        v[dk * 4 + dn * 2 + kk] = r;
                    }
            g_BFo[idx] = make_uint4(packbf(v[0], v[1]), packbf(v[2], v[3]),
                                    packbf(v[4], v[5]), packbf(v[6], v[7]));
        }
    }
}

// ---------------- degree count ----------------
__global__ void deg_count_kernel(const void* edges, int E) {
    int e = blockIdx.x * blockDim.x + threadIdx.x;
    if (e >= E) return;
    atomicAdd(&g_degi[edge_at(edges, (long long)E + e)], 1);
}

// ---------------- fused scan: block-local prefix + dinv; last block scans bsums ----------------
__global__ void scanA_kernel(int nblk) {
    __shared__ int sh[256];
    __shared__ int isLast;
    int t = threadIdx.x;
    int i = blockIdx.x * 256 + t;
    int v = (i < NN) ? g_degi[i] : 0;
    sh[t] = v;
    __syncthreads();
    int acc = v;
#pragma unroll
    for (int o = 1; o < 256; o <<= 1) {
        int add = (t >= o) ? sh[t - o] : 0;
        __syncthreads();
        acc += add;
        sh[t] = acc;
        __syncthreads();
    }
    if (i < NN) {
        g_row_ptr[i] = acc - v;
        g_dinv[i] = rsqrtf(1.0f + (float)v);
    }
    if (t == 255) {
        g_bsum[blockIdx.x] = acc;
        __threadfence();
        int tk = atomicAdd(&g_done[3], 1);
        isLast = (tk == (int)gridDim.x - 1);
    }
    __syncthreads();
    if (isLast && t < 32) {
        int base = t * 13;
        int vals[13];
        int s = 0;
#pragma unroll
        for (int q = 0; q < 13; q++) {
            int idx = base + q;
            vals[q] = (idx < nblk) ? __ldcg(&g_bsum[idx]) : 0;
            s += vals[q];
        }
        int incl = s;
#pragma unroll
        for (int o = 1; o < 32; o <<= 1) {
            int n = __shfl_up_sync(0xFFFFFFFFu, incl, o);
            if (t >= o) incl += n;
        }
        int run = incl - s;
#pragma unroll
        for (int q = 0; q < 13; q++) {
            int idx = base + q;
            if (idx < nblk) g_boff[idx] = run;
            run += vals[q];
        }
    }
}

// ---------------- CSR fill (boff inline) ----------------
__global__ void fill_kernel(const void* edges, int E) {
    int e = blockIdx.x * blockDim.x + threadIdx.x;
    if (e >= E) return;
    int s = edge_at(edges, e);
    int d = edge_at(edges, (long long)E + e);
    int rp = g_row_ptr[d] + g_boff[d >> 8];
    g_col[rp + atomicAdd(&g_cnt2[d], 1)] = s;
}

// ---------------- staging: 128 rows -> hi/lo bf16 images; optional fused normalize ----------------
__device__ __forceinline__ void stage128(const float* __restrict__ src, int row0,
                                         char* sA, int tid, int mode, int hasRes, int writeFeat,
                                         const float* __restrict__ gamma,
                                         const float* __restrict__ beta) {
#pragma unroll
    for (int j = 0; j < 8; j++) {
        int i = tid + j * 256;
        int rl = i >> 4;
        int c = i & 15;
        int rr = row0 + rl;
        int valid = rr < NN;
        float4 y0 = make_float4(0, 0, 0, 0), y1 = make_float4(0, 0, 0, 0);
        if (valid) {
            const float* sp = src + (size_t)rr * DD + c * 8;
            y0 = *(const float4*)sp;
            y1 = *(const float4*)(sp + 4);
        }
        if (mode) {
            float4 mu0 = ((const float4*)g_mu)[c * 2], mu1 = ((const float4*)g_mu)[c * 2 + 1];
            float4 rs0 = ((const float4*)g_rstd)[c * 2], rs1 = ((const float4*)g_rstd)[c * 2 + 1];
            float4 gm0 = ((const float4*)gamma)[c * 2], gm1 = ((const float4*)gamma)[c * 2 + 1];
            float4 be0 = ((const float4*)beta)[c * 2], be1v = ((const float4*)beta)[c * 2 + 1];
            y0.x = fmaxf(0.0f, (y0.x - mu0.x) * rs0.x * gm0.x + be0.x);
            y0.y = fmaxf(0.0f, (y0.y - mu0.y) * rs0.y * gm0.y + be0.y);
            y0.z = fmaxf(0.0f, (y0.z - mu0.z) * rs0.z * gm0.z + be0.z);
            y0.w = fmaxf(0.0f, (y0.w - mu0.w) * rs0.w * gm0.w + be0.w);
            y1.x = fmaxf(0.0f, (y1.x - mu1.x) * rs1.x * gm1.x + be1v.x);
            y1.y = fmaxf(0.0f, (y1.y - mu1.y) * rs1.y * gm1.y + be1v.y);
            y1.z = fmaxf(0.0f, (y1.z - mu1.z) * rs1.z * gm1.z + be1v.z);
            y1.w = fmaxf(0.0f, (y1.w - mu1.w) * rs1.w * gm1.w + be1v.w);
            if (hasRes && valid) {
                const float* rp = g_feat + (size_t)rr * DD + c * 8;
                float4 r0 = *(const float4*)rp, r1 = *(const float4*)(rp + 4);
                y0.x += r0.x; y0.y += r0.y; y0.z += r0.z; y0.w += r0.w;
                y1.x += r1.x; y1.y += r1.y; y1.z += r1.z; y1.w += r1.w;
            }
            float ss = y0.x * y0.x + y0.y * y0.y + y0.z * y0.z + y0.w * y0.w +
                       y1.x * y1.x + y1.y * y1.y + y1.z * y1.z + y1.w * y1.w;
#pragma unroll
            for (int o = 1; o < 16; o <<= 1) ss += __shfl_xor_sync(0xFFFFFFFFu, ss, o);
            float inv = 1.0f / fmaxf(sqrtf(ss), 1e-12f);
            y0.x *= inv; y0.y *= inv; y0.z *= inv; y0.w *= inv;
            y1.x *= inv; y1.y *= inv; y1.z *= inv; y1.w *= inv;
            if (writeFeat && valid) {
                float* fp = g_feat + (size_t)rr * DD + c * 8;
                *(float4*)fp = y0;
                *(float4*)(fp + 4) = y1;
            }
        }
        __nv_bfloat16 h0 = __float2bfloat16(y0.x), h1 = __float2bfloat16(y0.y);
        __nv_bfloat16 h2 = __float2bfloat16(y0.z), h3 = __float2bfloat16(y0.w);
        __nv_bfloat16 h4 = __float2bfloat16(y1.x), h5 = __float2bfloat16(y1.y);
        __nv_bfloat16 h6 = __float2bfloat16(y1.z), h7 = __float2bfloat16(y1.w);
        uint4 hv = make_uint4(packbf(h0, h1), packbf(h2, h3), packbf(h4, h5), packbf(h6, h7));
        uint4 lv = make_uint4(
            pack2(y0.x - __bfloat162float(h0), y0.y - __bfloat162float(h1)),
            pack2(y0.z - __bfloat162float(h2), y0.w - __bfloat162float(h3)),
            pack2(y1.x - __bfloat162float(h4), y1.y - __bfloat162float(h5)),
            pack2(y1.z - __bfloat162float(h6), y1.w - __bfloat162float(h7)));
        uint32_t off = (uint32_t)rl * 256u + (((uint32_t)(c ^ (rl & 7))) << 4);
        *(uint4*)(sA + off) = hv;
        *(uint4*)(sA + 32768 + off) = lv;
    }
}

// ---------------- main GEMM: fused 3-pass mainloop, M=128 tiles ----------------
#define SMG_TOTAL 65536
__global__ __launch_bounds__(256, 2) void gemm_mma_kernel(const float* __restrict__ src, int layer,
                                                          int mode, int hasRes, int writeFeat,
                                                          const float* __restrict__ gamma,
                                                          const float* __restrict__ beta) {
    extern __shared__ char smem[];
    uint32_t sb = smem_u32(smem);
    int tid = threadIdx.x, lane = tid & 31, wid = tid >> 5;
    int row0 = blockIdx.x * 128;

    stage128(src, row0, smem, tid, mode, hasRes, writeFeat, gamma, beta);
    __syncthreads();

    const int wm = (wid & 3) * 32;
    const int ng = wid >> 2;
    float acc[2][8][4];
#pragma unroll
    for (int mt = 0; mt < 2; mt++)
#pragma unroll
        for (int nt = 0; nt < 8; nt++)
#pragma unroll
            for (int q = 0; q < 4; q++) acc[mt][nt][q] = 0.0f;

    const uint4* __restrict__ BFh = g_BF[layer] + (ng * 8) * 128 + lane;
    const uint4* __restrict__ BFl = g_BF[layer] + ((2 + ng) * 8) * 128 + lane;

#pragma unroll
    for (int ks = 0; ks < 8; ks++) {
        uint32_t ah[2][4], al[2][4];
#pragma unroll
        for (int mt = 0; mt < 2; mt++) {
            int m = wm + mt * 16 + (lane & 15);
            uint32_t addr = sb + m * 256 + ((((ks << 1) | (lane >> 4)) ^ (m & 7)) << 4);
            LDSM_X4(ah[mt], addr);
            LDSM_X4(al[mt], addr + 32768);
        }
        uint4 bh[4];
#pragma unroll
        for (int p = 0; p < 4; p++) bh[p] = BFh[ks * 128 + p * 32];
#pragma unroll
        for (int p = 0; p < 4; p++)
#pragma unroll
            for (int mt = 0; mt < 2; mt++) {
                MMA16816(acc[mt][2 * p], ah[mt], bh[p].x, bh[p].z);
                MMA16816(acc[mt][2 * p + 1], ah[mt], bh[p].y, bh[p].w);
            }
#pragma unroll
        for (int p = 0; p < 4; p++)
#pragma unroll
            for (int mt = 0; mt < 2; mt++) {
                MMA16816(acc[mt][2 * p], al[mt], bh[p].x, bh[p].z);
                MMA16816(acc[mt][2 * p + 1], al[mt], bh[p].y, bh[p].w);
            }
        uint4 bl[4];
#pragma unroll
        for (int p = 0; p < 4; p++) bl[p] = BFl[ks * 128 + p * 32];
#pragma unroll
        for (int p = 0; p < 4; p++)
#pragma unroll
            for (int mt = 0; mt < 2; mt++) {
                MMA16816(acc[mt][2 * p], ah[mt], bl[p].x, bl[p].z);
                MMA16816(acc[mt][2 * p + 1], ah[mt], bl[p].y, bl[p].w);
            }
    }

#pragma unroll
    for (int mt = 0; mt < 2; mt++) {
        int rA = row0 + wm + mt * 16 + (lane >> 2);
        int rB = rA + 8;
#pragma unroll
        for (int nt = 0; nt < 8; nt++) {
            int col = ng * 64 + nt * 8 + (lane & 3) * 2;
            if (rA < NN)
                *(float2*)(g_h + (size_t)rA * DD + col) = make_float2(acc[mt][nt][0], acc[mt][nt][1]);
            if (rB < NN)
                *(float2*)(g_h + (size_t)rB * DD + col) = make_float2(acc[mt][nt][2], acc[mt][nt][3]);
        }
    }
}

// ---------------- output head ----------------
__global__ __launch_bounds__(256, 2) void head_kernel(const float* __restrict__ bout,
                                                      float* __restrict__ out,
                                                      const float* __restrict__ gamma,
                                                      const float* __restrict__ beta) {
    extern __shared__ char smem[];
    uint32_t sb = smem_u32(smem);
    int tid = threadIdx.x, lane = tid & 31, wid = tid >> 5;
    int row0 = blockIdx.x * 128;

    stage128(g_agg, row0, smem, tid, 1, 1, 0, gamma, beta);
    __syncthreads();

    const int wm = (wid & 3) * 32;
    const int ng = wid >> 2;
    float acc[2][4][4];
#pragma unroll
    for (int mt = 0; mt < 2; mt++)
#pragma unroll
        for (int nt = 0; nt < 4; nt++)
#pragma unroll
            for (int q = 0; q < 4; q++) acc[mt][nt][q] = 0.0f;

    const uint4* __restrict__ BFh = g_BFo + lane;
    const uint4* __restrict__ BFl = g_BFo + 8 * 128 + lane;

#pragma unroll
    for (int ks = 0; ks < 8; ks++) {
        uint32_t ah[2][4], al[2][4];
#pragma unroll
        for (int mt = 0; mt < 2; mt++) {
            int m = wm + mt * 16 + (lane & 15);
            uint32_t addr = sb + m * 256 + ((((ks << 1) | (lane >> 4)) ^ (m & 7)) << 4);
            LDSM_X4(ah[mt], addr);
            LDSM_X4(al[mt], addr + 32768);
        }
        uint4 bh[2], bl[2];
#pragma unroll
        for (int pp = 0; pp < 2; pp++) {
            int p = ng * 2 + pp;
            bh[pp] = BFh[ks * 128 + p * 32];
            bl[pp] = BFl[ks * 128 + p * 32];
        }
#pragma unroll
        for (int pp = 0; pp < 2; pp++)
#pragma unroll
            for (int mt = 0; mt < 2; mt++) {
                MMA16816(acc[mt][2 * pp], ah[mt], bh[pp].x, bh[pp].z);
                MMA16816(acc[mt][2 * pp + 1], ah[mt], bh[pp].y, bh[pp].w);
                MMA16816(acc[mt][2 * pp], al[mt], bh[pp].x, bh[pp].z);
                MMA16816(acc[mt][2 * pp + 1], al[mt], bh[pp].y, bh[pp].w);
                MMA16816(acc[mt][2 * pp], ah[mt], bl[pp].x, bl[pp].z);
                MMA16816(acc[mt][2 * pp + 1], ah[mt], bl[pp].y, bl[pp].w);
            }
    }

#pragma unroll
    for (int mt = 0; mt < 2; mt++) {
        int rA = row0 + wm + mt * 16 + (lane >> 2);
        int rB = rA + 8;
#pragma unroll
        for (int pp = 0; pp < 2; pp++)
#pragma unroll
            for (int q = 0; q < 2; q++) {
                int col = (ng * 2 + pp) * 16 + q * 8 + (lane & 3) * 2;
                float* a4 = acc[mt][2 * pp + q];
                if (col < CC) {
                    float b0 = bout[col], b1 = bout[col + 1];
                    if (rA < NN)
                        *(float2*)(out + (size_t)rA * CC + col) = make_float2(a4[0] + b0, a4[1] + b1);
                    if (rB < NN)
                        *(float2*)(out + (size_t)rB * CC + col) = make_float2(a4[2] + b0, a4[3] + b1);
                }
            }
    }
}

// ---------------- CSR aggregation (warp per row, 8 rows/warp) + fused BN stats + finalize ----------------
__global__ __launch_bounds__(256) void agg_kernel(int layer, int E) {
    __shared__ float ssum[128], ssq[128];
    __shared__ int isLast;
    int tid = threadIdx.x;
    if (tid < 128) { ssum[tid] = 0.0f; ssq[tid] = 0.0f; }
    __syncthreads();
    int wid = tid >> 5, lane = tid & 31;
    float4 psum = make_float4(0, 0, 0, 0);
    float4 psq = make_float4(0, 0, 0, 0);
    int rbase = blockIdx.x * 64 + wid * 8;
#pragma unroll 1
    for (int it = 0; it < 8; it++) {
        int r = rbase + it;
        if (r >= NN) break;
        int beg = g_row_ptr[r] + g_boff[r >> 8];
        int end = (r == NN - 1) ? E : (g_row_ptr[r + 1] + g_boff[(r + 1) >> 8]);
        float dr = g_dinv[r];
        float4 acc = ((const float4*)(g_h + (size_t)r * DD))[lane];
        float d2 = dr * dr;
        acc.x *= d2; acc.y *= d2; acc.z *= d2; acc.w *= d2;
        for (int base = beg; base < end; base += 8) {
            int m = end - base;
            if (m > 8) m = 8;
            int c = 0;
            float w = 0.0f;
            if (lane < m) { c = g_col[base + lane]; w = g_dinv[c] * dr; }
            float4 vv[8];
#pragma unroll
            for (int j = 0; j < 8; j++)
                if (j < m) {
                    int sj = __shfl_sync(0xFFFFFFFFu, c, j);
                    vv[j] = __ldg((const float4*)(g_h + (size_t)sj * DD + lane * 4));
                }
#pragma unroll
            for (int j = 0; j < 8; j++)
                if (j < m) {
                    float wj = __shfl_sync(0xFFFFFFFFu, w, j);
                    acc.x += vv[j].x * wj; acc.y += vv[j].y * wj;
                    acc.z += vv[j].z * wj; acc.w += vv[j].w * wj;
                }
        }
        ((float4*)(g_agg + (size_t)r * DD))[lane] = acc;
        psum.x += acc.x; psum.y += acc.y; psum.z += acc.z; psum.w += acc.w;
        psq.x += acc.x * acc.x; psq.y += acc.y * acc.y;
        psq.z += acc.z * acc.z; psq.w += acc.w * acc.w;
    }
    int c0 = lane * 4;
    atomicAdd(&ssum[c0 + 0], psum.x); atomicAdd(&ssum[c0 + 1], psum.y);
    atomicAdd(&ssum[c0 + 2], psum.z); atomicAdd(&ssum[c0 + 3], psum.w);
    atomicAdd(&ssq[c0 + 0], psq.x);  atomicAdd(&ssq[c0 + 1], psq.y);
    atomicAdd(&ssq[c0 + 2], psq.z);  atomicAdd(&ssq[c0 + 3], psq.w);
    __syncthreads();
    if (tid < 128) {
        atomicAdd(&g_statsAll[layer * 256 + tid], ssum[tid]);
        atomicAdd(&g_statsAll[layer * 256 + 128 + tid], ssq[tid]);
    }
    __threadfence();
    if (tid == 0) {
        int tk = atomicAdd(&g_done[layer], 1);
        isLast = (tk == (int)gridDim.x - 1);
    }
    __syncthreads();
    if (isLast && tid < 128) {
        float inv_n = 1.0f / (float)NN;
        float mu = __ldcg(&g_statsAll[layer * 256 + tid]) * inv_n;
        float var = __ldcg(&g_statsAll[layer * 256 + 128 + tid]) * inv_n - mu * mu;
        g_mu[tid] = mu;
        g_rstd[tid] = rsqrtf(var + 1e-5f);
    }
}

// ---------------- launch (two-stream overlap: CSR build || fragment prep + gemm1) ----------------
extern "C" void kernel_launch(void* const* d_in, const int* in_sizes, int n_in,
                              void* d_out, int out_size) {
    const float* x    = (const float*)d_in[0];
    const void*  edges = d_in[1];
    const float* W1   = (const float*)d_in[2];
    const float* W2   = (const float*)d_in[4];
    const float* W3   = (const float*)d_in[6];
    const float* g1   = (const float*)d_in[8];
    const float* be1  = (const float*)d_in[9];
    const float* g2   = (const float*)d_in[10];
    const float* be2  = (const float*)d_in[11];
    const float* g3   = (const float*)d_in[12];
    const float* be3  = (const float*)d_in[13];
    const float* Wout = (const float*)d_in[14];
    const float* bout = (const float*)d_in[15];
    float* out = (float*)d_out;
    int E = in_sizes[1] / 2;

    float* aggp = nullptr;
    cudaGetSymbolAddress((void**)&aggp, g_agg);

    cudaFuncSetAttribute(gemm_mma_kernel, cudaFuncAttributeMaxDynamicSharedMemorySize, SMG_TOTAL);
    cudaFuncSetAttribute(head_kernel, cudaFuncAttributeMaxDynamicSharedMemorySize, SMG_TOTAL);

    // lazily-created side stream + events (host-side handles only; no device memory)
    static cudaStream_t s1 = nullptr;
    static cudaEvent_t evFork = nullptr, evJoin = nullptr;
    if (s1 == nullptr) {
        cudaStreamCreateWithFlags(&s1, cudaStreamNonBlocking);
        cudaEventCreateWithFlags(&evFork, cudaEventDisableTiming);
        cudaEventCreateWithFlags(&evJoin, cudaEventDisableTiming);
    }

    int nblk = (NN + 255) / 256;      // 391
    int gblk = (NN + 127) / 128;      // 782
    int eblk = (E + 255) / 256;
    int agg_blk = (NN + 63) / 64;     // 1563

    // main: init -> prepw -> gemm1 ; side: deg_count -> scanA -> fill
    init_kernel<<<99, 512>>>(edges);                        // launch #1
    cudaEventRecord(evFork, 0);
    cudaStreamWaitEvent(s1, evFork, 0);
    deg_count_kernel<<<eblk, 256, 0, s1>>>(edges, E);       // #2 (side)
    prepw_kernel<<<25, 512>>>(W1, W2, W3, Wout);            // #3 (main)
    gemm_mma_kernel<<<gblk, 256, SMG_TOTAL>>>(x, 0, 0, 0, 0, nullptr, nullptr);  // #4 (ncu slot)
    scanA_kernel<<<nblk, 256, 0, s1>>>(nblk);               // #5 (side)
    fill_kernel<<<eblk, 256, 0, s1>>>(edges, E);            // #6 (side)
    cudaEventRecord(evJoin, s1);
    cudaStreamWaitEvent(0, evJoin, 0);

    agg_kernel<<<agg_blk, 256>>>(0, E);
    gemm_mma_kernel<<<gblk, 256, SMG_TOTAL>>>(aggp, 1, 1, 0, 1, g1, be1);

    agg_kernel<<<agg_blk, 256>>>(1, E);
    gemm_mma_kernel<<<gblk, 256, SMG_TOTAL>>>(aggp, 2, 1, 1, 1, g2, be2);

    agg_kernel<<<agg_blk, 256>>>(2, E);
    head_kernel<<<gblk, 256, SMG_TOTAL>>>(bout, out, g3, be3);
}